// round 4
// baseline (speedup 1.0000x reference)
#include <cuda_runtime.h>
#include <cuda_fp16.h>
#include <cstdint>

// ============================================================================
// GraphConvolution on plain-target sm_103 (no tcgen05 available in this
// toolchain's PTX target): fp16 mma.sync GEMM with fused fp32 adj pre-mixing.
//   H[4b+n,:] = sum_m adj[n,m]*F[4b+m,:]   (fp32, via warp shuffles at load)
//   out = H @ W^T + bias                   (fp16 inputs, fp32 accumulate)
// CTA tile 128x256xK, 512 threads (16 warps, 4x4), warp tile 32x64.
// ============================================================================

#define KDIM    1024
#define NOUTD   256
#define MTILE   128
#define KC      64
#define NCHUNK  (KDIM / KC)          // 16
#define THREADS 512
#define ABYTES  (128 * 128)          // 128 rows x 64 fp16
#define BBYTES  (256 * 128)          // 256 rows x 64 fp16
#define SLOTB   (ABYTES + BBYTES)    // 49152
#define SMEMB   (2 * SLOTB)          // 98304

__device__ __align__(16) __half WhalfG[NOUTD * KDIM];   // 512 KB scratch

// ---------------- helpers ----------------
__device__ __forceinline__ uint32_t smem_u32(const void* p) {
    uint32_t a;
    asm("{ .reg .u64 t; cvta.to.shared.u64 t, %1; cvt.u32.u64 %0, t; }" : "=r"(a) : "l"(p));
    return a;
}
__device__ __forceinline__ uint32_t swz(int row, int colbyte) {
    return (uint32_t)(row * 128 + (colbyte ^ ((row & 7) << 4)));
}
__device__ __forceinline__ void ldmatrix_x4(uint32_t& r0, uint32_t& r1,
                                            uint32_t& r2, uint32_t& r3, uint32_t addr) {
    asm volatile("ldmatrix.sync.aligned.m8n8.x4.shared.b16 {%0,%1,%2,%3}, [%4];"
                 : "=r"(r0), "=r"(r1), "=r"(r2), "=r"(r3) : "r"(addr));
}
__device__ __forceinline__ void mma16816(float* c, const uint32_t* a,
                                         uint32_t b0, uint32_t b1) {
    asm volatile("mma.sync.aligned.m16n8k16.row.col.f32.f16.f16.f32 "
                 "{%0,%1,%2,%3}, {%4,%5,%6,%7}, {%8,%9}, {%0,%1,%2,%3};"
                 : "+f"(c[0]), "+f"(c[1]), "+f"(c[2]), "+f"(c[3])
                 : "r"(a[0]), "r"(a[1]), "r"(a[2]), "r"(a[3]), "r"(b0), "r"(b1));
}
__device__ __forceinline__ uint32_t h2u(__half2 h) {
    return *reinterpret_cast<uint32_t*>(&h);
}

// ---------------- kernel 1: W fp32 -> fp16 ----------------
__global__ void convW_kernel(const float* __restrict__ W) {
    int i = blockIdx.x * blockDim.x + threadIdx.x;        // 65536 threads, 4 f each
    float4 v = reinterpret_cast<const float4*>(W)[i];
    __half2 h0 = __floats2half2_rn(v.x, v.y);
    __half2 h1 = __floats2half2_rn(v.z, v.w);
    uint2 u = make_uint2(h2u(h0), h2u(h1));
    reinterpret_cast<uint2*>(WhalfG)[i] = u;
}

// ---------------- kernel 2: fused premix + GEMM ----------------
__global__ void __launch_bounds__(THREADS, 1) gconv_gemm_kernel(
    const float* __restrict__ adj,   // [4,4]
    const float* __restrict__ F,     // [32768,1024]
    const float* __restrict__ bias,  // [256]
    float* __restrict__ out)         // [32768,256]
{
    extern __shared__ char smem[];
    const uint32_t sbase = smem_u32(smem);
    const int tid  = threadIdx.x;
    const int warp = tid >> 5;
    const int lane = tid & 31;
    const int wm   = warp & 3;       // 4 warps along M
    const int wn   = warp >> 2;      // 4 warps along N
    const size_t tile_row = (size_t)blockIdx.x * MTILE;

    // adj row for this thread's output row (row = tid>>2, n' = row&3)
    const int arow = ((tid >> 2) & 3) * 4;
    float am0 = __ldg(adj + arow + 0), am1 = __ldg(adj + arow + 1),
          am2 = __ldg(adj + arow + 2), am3 = __ldg(adj + arow + 3);

    // accumulators: [mf][nf][4]
    float c[2][8][4];
#pragma unroll
    for (int i = 0; i < 2; i++)
#pragma unroll
        for (int j = 0; j < 8; j++)
#pragma unroll
            for (int k = 0; k < 4; k++) c[i][j][k] = 0.f;

    float4 ra[4];   // A staging (held across MMA phase)

    // ---- A: global load (row = tid>>2, 16 floats along K) ----
    auto loadA = [&](int ch) {
        const float* ap = F + (tile_row + (tid >> 2)) * (size_t)KDIM
                            + ch * KC + (tid & 3) * 16;
#pragma unroll
        for (int i = 0; i < 4; i++)
            ra[i] = reinterpret_cast<const float4*>(ap)[i];
    };

    // ---- A: premix (shfl) + fp16 convert + STS ----
    auto storeA = [&](int slot) {
        char* sa = smem + slot * SLOTB;
        const int row = tid >> 2;
#pragma unroll
        for (int i = 0; i < 4; i++) {
            float4 v = ra[i];
            float ox = 0.f, oy = 0.f, oz = 0.f, ow = 0.f;
#pragma unroll
            for (int m = 0; m < 4; m++) {
                const int src = (lane & 19) | (m << 2);
                const float a = (m == 0) ? am0 : (m == 1) ? am1 : (m == 2) ? am2 : am3;
                ox += a * __shfl_sync(0xffffffffu, v.x, src);
                oy += a * __shfl_sync(0xffffffffu, v.y, src);
                oz += a * __shfl_sync(0xffffffffu, v.z, src);
                ow += a * __shfl_sync(0xffffffffu, v.w, src);
            }
            uint2 u = make_uint2(h2u(__floats2half2_rn(ox, oy)),
                                 h2u(__floats2half2_rn(oz, ow)));
            const int cb = (tid & 3) * 32 + i * 8;
            *reinterpret_cast<uint2*>(sa + swz(row, cb)) = u;
        }
    };

    // ---- B: global (fp16, L2-hot) load + STS ----
    auto loadB = [&](int ch, int slot) {
        char* sb = smem + slot * SLOTB + ABYTES;
        const int row = tid >> 1;
        const int cbase = (tid & 1) * 64;
        const char* bp = reinterpret_cast<const char*>(WhalfG)
                         + (size_t)row * 2048 + ch * 128 + cbase;
        uint4 t0 = reinterpret_cast<const uint4*>(bp)[0];
        uint4 t1 = reinterpret_cast<const uint4*>(bp)[1];
        uint4 t2 = reinterpret_cast<const uint4*>(bp)[2];
        uint4 t3 = reinterpret_cast<const uint4*>(bp)[3];
        *reinterpret_cast<uint4*>(sb + swz(row, cbase +  0)) = t0;
        *reinterpret_cast<uint4*>(sb + swz(row, cbase + 16)) = t1;
        *reinterpret_cast<uint4*>(sb + swz(row, cbase + 32)) = t2;
        *reinterpret_cast<uint4*>(sb + swz(row, cbase + 48)) = t3;
    };

    // ---- prologue: fill slot 0 ----
    loadA(0);
    storeA(0);
    loadB(0, 0);

    // ---- main loop ----
    for (int ch = 0; ch < NCHUNK; ch++) {
        __syncthreads();                    // slot (ch&1) ready; prev slot free
        if (ch + 1 < NCHUNK) loadA(ch + 1); // issue DRAM loads, land during MMA

        const uint32_t sa = sbase + (ch & 1) * SLOTB;
        const uint32_t sb = sa + ABYTES;
#pragma unroll
        for (int ks = 0; ks < 4; ks++) {
            uint32_t a[2][4];
#pragma unroll
            for (int mf = 0; mf < 2; mf++) {
                const int row = wm * 32 + mf * 16 + (lane & 15);
                const int cb  = ks * 32 + ((lane >> 4) & 1) * 16;
                ldmatrix_x4(a[mf][0], a[mf][1], a[mf][2], a[mf][3], sa + swz(row, cb));
            }
            uint32_t b[4][4];
#pragma unroll
            for (int j = 0; j < 4; j++) {
                const int row = wn * 64 + j * 16 + (lane & 7) + ((lane >> 4) & 1) * 8;
                const int cb  = ks * 32 + ((lane >> 3) & 1) * 16;
                ldmatrix_x4(b[j][0], b[j][1], b[j][2], b[j][3], sb + swz(row, cb));
            }
#pragma unroll
            for (int mf = 0; mf < 2; mf++)
#pragma unroll
                for (int nf = 0; nf < 8; nf++)
                    mma16816(c[mf][nf], a[mf],
                             b[nf >> 1][(nf & 1) * 2], b[nf >> 1][(nf & 1) * 2 + 1]);
        }

        if (ch + 1 < NCHUNK) {
            storeA((ch + 1) & 1);           // A data arrived during MMA
            loadB(ch + 1, (ch + 1) & 1);    // short L2 latency, then loop barrier
        }
    }

    // ---- epilogue: + bias, store fp32 ----
    float2 bb[8];
#pragma unroll
    for (int nf = 0; nf < 8; nf++)
        bb[nf] = *reinterpret_cast<const float2*>(bias + wn * 64 + nf * 8 + (lane & 3) * 2);

#pragma unroll
    for (int mf = 0; mf < 2; mf++) {
#pragma unroll
        for (int nf = 0; nf < 8; nf++) {
            const size_t m = tile_row + wm * 32 + mf * 16 + (lane >> 2);
            const int n = wn * 64 + nf * 8 + (lane & 3) * 2;
            float2 o0 = make_float2(c[mf][nf][0] + bb[nf].x, c[mf][nf][1] + bb[nf].y);
            float2 o1 = make_float2(c[mf][nf][2] + bb[nf].x, c[mf][nf][3] + bb[nf].y);
            *reinterpret_cast<float2*>(out + m * NOUTD + n) = o0;
            *reinterpret_cast<float2*>(out + (m + 8) * NOUTD + n) = o1;
        }
    }
}

// ============================================================================
extern "C" void kernel_launch(void* const* d_in, const int* in_sizes, int n_in,
                              void* d_out, int out_size) {
    (void)in_sizes; (void)n_in; (void)out_size;
    const float* adj  = (const float*)d_in[0];   // [4,4]
    const float* F    = (const float*)d_in[1];   // [8192,4,1024]
    const float* W    = (const float*)d_in[2];   // [256,1024]
    const float* bias = (const float*)d_in[3];   // [256]
    float* out = (float*)d_out;                  // [8192,4,256]

    convW_kernel<<<256, 256>>>(W);

    cudaFuncSetAttribute(gconv_gemm_kernel,
                         cudaFuncAttributeMaxDynamicSharedMemorySize, SMEMB);
    gconv_gemm_kernel<<<32768 / MTILE, THREADS, SMEMB>>>(adj, F, bias, out);
}

// round 6
// speedup vs baseline: 1.2031x; 1.2031x over previous
#include <cuda_runtime.h>
#include <cuda_fp16.h>
#include <cstdint>

// ============================================================================
// GraphConvolution: out = (adj-premixed F) @ W^T + bias, fp16 MMA, fp32 accum.
// R5 resubmit (infra failure): 256-thread CTA (M64 x N256), 2 CTAs/SM,
// cp.async 3-stage B ring, register-double-buffered premixed A.
// Warp tile 32x64 (8 warps, 2Mx4N).
// ============================================================================

#define KDIM    1024
#define NOUTD   256
#define MTILE   64
#define KC      64
#define NCHUNK  (KDIM / KC)          // 16
#define THREADS 256
#define ASLOT   (64 * 128)           // 8 KB per A slot (fp16, 128B rows)
#define BSTAGE  (256 * 128)          // 32 KB per B stage
#define SMEM_B0 (2 * ASLOT)          // 16384
#define SMEMB   (SMEM_B0 + 3 * BSTAGE)  // 114688 = 112 KB

__device__ __align__(16) __half WhalfG[NOUTD * KDIM];   // 512 KB scratch

// ---------------- helpers ----------------
__device__ __forceinline__ uint32_t smem_u32(const void* p) {
    uint32_t a;
    asm("{ .reg .u64 t; cvta.to.shared.u64 t, %1; cvt.u32.u64 %0, t; }" : "=r"(a) : "l"(p));
    return a;
}
__device__ __forceinline__ uint32_t swz(int row, int colbyte) {
    return (uint32_t)(row * 128 + (colbyte ^ ((row & 7) << 4)));
}
__device__ __forceinline__ void ldmatrix_x4(uint32_t& r0, uint32_t& r1,
                                            uint32_t& r2, uint32_t& r3, uint32_t addr) {
    asm volatile("ldmatrix.sync.aligned.m8n8.x4.shared.b16 {%0,%1,%2,%3}, [%4];"
                 : "=r"(r0), "=r"(r1), "=r"(r2), "=r"(r3) : "r"(addr));
}
__device__ __forceinline__ void mma16816(float* c, const uint32_t* a,
                                         uint32_t b0, uint32_t b1) {
    asm volatile("mma.sync.aligned.m16n8k16.row.col.f32.f16.f16.f32 "
                 "{%0,%1,%2,%3}, {%4,%5,%6,%7}, {%8,%9}, {%0,%1,%2,%3};"
                 : "+f"(c[0]), "+f"(c[1]), "+f"(c[2]), "+f"(c[3])
                 : "r"(a[0]), "r"(a[1]), "r"(a[2]), "r"(a[3]), "r"(b0), "r"(b1));
}
__device__ __forceinline__ uint32_t h2u(__half2 h) {
    return *reinterpret_cast<uint32_t*>(&h);
}
__device__ __forceinline__ void cp_async16(uint32_t dst, const void* src) {
    asm volatile("cp.async.cg.shared.global [%0], [%1], 16;" :: "r"(dst), "l"(src));
}
#define CP_COMMIT() asm volatile("cp.async.commit_group;" ::: "memory")
#define CP_WAIT1()  asm volatile("cp.async.wait_group 1;" ::: "memory")

// ---------------- kernel 1: W fp32 -> fp16 ----------------
__global__ void convW_kernel(const float* __restrict__ W) {
    int i = blockIdx.x * blockDim.x + threadIdx.x;        // 65536 threads, 4 f each
    float4 v = reinterpret_cast<const float4*>(W)[i];
    uint2 u = make_uint2(h2u(__floats2half2_rn(v.x, v.y)),
                         h2u(__floats2half2_rn(v.z, v.w)));
    reinterpret_cast<uint2*>(WhalfG)[i] = u;
}

// ---------------- kernel 2: fused premix + GEMM ----------------
__global__ void __launch_bounds__(THREADS, 2) gconv_gemm_kernel(
    const float* __restrict__ adj,   // [4,4]
    const float* __restrict__ F,     // [32768,1024]
    const float* __restrict__ bias,  // [256]
    float* __restrict__ out)         // [32768,256]
{
    extern __shared__ char smem[];
    const uint32_t sbase = smem_u32(smem);
    const int tid  = threadIdx.x;
    const int warp = tid >> 5;
    const int lane = tid & 31;
    const int wm   = warp & 1;       // 2 warps along M
    const int wn   = warp >> 1;      // 4 warps along N
    const size_t tile_row = (size_t)blockIdx.x * MTILE;

    // adj row for this thread's output row (row = tid>>2, n' = row&3)
    const int arow = ((tid >> 2) & 3) * 4;
    const float am0 = __ldg(adj + arow + 0), am1 = __ldg(adj + arow + 1),
                am2 = __ldg(adj + arow + 2), am3 = __ldg(adj + arow + 3);

    float c[2][8][4];
#pragma unroll
    for (int i = 0; i < 2; i++)
#pragma unroll
        for (int j = 0; j < 8; j++)
#pragma unroll
            for (int k = 0; k < 4; k++) c[i][j][k] = 0.f;

    float4 ra[4];   // A staging: 16 floats (one row-chunk segment)

    // ---- A: global load (row = tid>>2, 16 consecutive floats along K) ----
    auto loadA = [&](int ch) {
        const float* ap = F + (tile_row + (tid >> 2)) * (size_t)KDIM
                            + ch * KC + (tid & 3) * 16;
#pragma unroll
        for (int i = 0; i < 4; i++)
            ra[i] = reinterpret_cast<const float4*>(ap)[i];
    };

    // ---- A: premix (shfl) + fp16 convert + STS (32B per thread) ----
    auto storeA = [&](int slot) {
        char* sa = smem + slot * ASLOT;
        const int row = tid >> 2;
        uint32_t h[8];
#pragma unroll
        for (int i = 0; i < 4; i++) {
            float4 v = ra[i];
            float ox = 0.f, oy = 0.f, oz = 0.f, ow = 0.f;
#pragma unroll
            for (int m = 0; m < 4; m++) {
                const int src = (lane & 19) | (m << 2);
                const float a = (m == 0) ? am0 : (m == 1) ? am1 : (m == 2) ? am2 : am3;
                ox += a * __shfl_sync(0xffffffffu, v.x, src);
                oy += a * __shfl_sync(0xffffffffu, v.y, src);
                oz += a * __shfl_sync(0xffffffffu, v.z, src);
                ow += a * __shfl_sync(0xffffffffu, v.w, src);
            }
            h[i * 2 + 0] = h2u(__floats2half2_rn(ox, oy));
            h[i * 2 + 1] = h2u(__floats2half2_rn(oz, ow));
        }
        const int cb = (tid & 3) * 32;
        *reinterpret_cast<uint4*>(sa + swz(row, cb)) =
            make_uint4(h[0], h[1], h[2], h[3]);
        *reinterpret_cast<uint4*>(sa + swz(row, cb + 16)) =
            make_uint4(h[4], h[5], h[6], h[7]);
    };

    // ---- B: cp.async fp16 W chunk into smem stage (128B per thread) ----
    auto cpasyncB = [&](int ch, int stage) {
        const uint32_t bs = sbase + SMEM_B0 + stage * BSTAGE;
#pragma unroll
        for (int i = 0; i < 8; i++) {
            const int u = tid + i * THREADS;     // 0..2047
            const int row = u >> 3;              // 0..255
            const int cb  = (u & 7) * 16;        // 0..112
            const char* src = reinterpret_cast<const char*>(WhalfG)
                              + (size_t)row * 2048 + ch * 128 + cb;
            cp_async16(bs + swz(row, cb), src);
        }
    };

    // ---- prologue ----
    cpasyncB(0, 0); CP_COMMIT();
    cpasyncB(1, 1); CP_COMMIT();
    loadA(0); storeA(0);
    loadA(1);

    // ---- main loop ----
    for (int ch = 0; ch < NCHUNK; ch++) {
        CP_WAIT1();                 // B(ch) arrived (B(ch+1) may be in flight)
        __syncthreads();            // A(ch) STS + B visible; MMA(ch-1) done

        if (ch + 2 < NCHUNK) cpasyncB(ch + 2, (ch + 2) % 3);
        CP_COMMIT();                // commit every iter -> constant wait depth
        if (ch + 1 < NCHUNK) storeA((ch + 1) & 1);
        if (ch + 2 < NCHUNK) loadA(ch + 2);

        const uint32_t sa = sbase + (ch & 1) * ASLOT;
        const uint32_t sb = sbase + SMEM_B0 + (ch % 3) * BSTAGE;
#pragma unroll
        for (int ks = 0; ks < 4; ks++) {
            uint32_t a[2][4];
#pragma unroll
            for (int mf = 0; mf < 2; mf++) {
                const int row = wm * 32 + mf * 16 + (lane & 15);
                const int cb  = ks * 32 + ((lane >> 4) & 1) * 16;
                ldmatrix_x4(a[mf][0], a[mf][1], a[mf][2], a[mf][3], sa + swz(row, cb));
            }
            uint32_t b[4][4];
#pragma unroll
            for (int j = 0; j < 4; j++) {
                const int row = wn * 64 + j * 16 + (lane & 7) + ((lane >> 4) & 1) * 8;
                const int cb  = ks * 32 + ((lane >> 3) & 1) * 16;
                ldmatrix_x4(b[j][0], b[j][1], b[j][2], b[j][3], sb + swz(row, cb));
            }
#pragma unroll
            for (int mf = 0; mf < 2; mf++)
#pragma unroll
                for (int nf = 0; nf < 8; nf++)
                    mma16816(c[mf][nf], a[mf],
                             b[nf >> 1][(nf & 1) * 2], b[nf >> 1][(nf & 1) * 2 + 1]);
        }
    }

    // ---- epilogue: + bias, store fp32 ----
    float2 bb[8];
#pragma unroll
    for (int nf = 0; nf < 8; nf++)
        bb[nf] = *reinterpret_cast<const float2*>(bias + wn * 64 + nf * 8 + (lane & 3) * 2);

#pragma unroll
    for (int mf = 0; mf < 2; mf++) {
#pragma unroll
        for (int nf = 0; nf < 8; nf++) {
            const size_t m = tile_row + wm * 32 + mf * 16 + (lane >> 2);
            const int n = wn * 64 + nf * 8 + (lane & 3) * 2;
            float2 o0 = make_float2(c[mf][nf][0] + bb[nf].x, c[mf][nf][1] + bb[nf].y);
            float2 o1 = make_float2(c[mf][nf][2] + bb[nf].x, c[mf][nf][3] + bb[nf].y);
            *reinterpret_cast<float2*>(out + m * NOUTD + n) = o0;
            *reinterpret_cast<float2*>(out + (m + 8) * NOUTD + n) = o1;
        }
    }
}

// ============================================================================
extern "C" void kernel_launch(void* const* d_in, const int* in_sizes, int n_in,
                              void* d_out, int out_size) {
    (void)in_sizes; (void)n_in; (void)out_size;
    const float* adj  = (const float*)d_in[0];   // [4,4]
    const float* F    = (const float*)d_in[1];   // [8192,4,1024]
    const float* W    = (const float*)d_in[2];   // [256,1024]
    const float* bias = (const float*)d_in[3];   // [256]
    float* out = (float*)d_out;                  // [8192,4,256]

    convW_kernel<<<256, 256>>>(W);

    cudaFuncSetAttribute(gconv_gemm_kernel,
                         cudaFuncAttributeMaxDynamicSharedMemorySize, SMEMB);
    gconv_gemm_kernel<<<32768 / MTILE, THREADS, SMEMB>>>(adj, F, bias, out);
}

// round 7
// speedup vs baseline: 1.6917x; 1.4061x over previous
#include <cuda_runtime.h>
#include <cuda_fp16.h>
#include <cstdint>

// ============================================================================
// GraphConvolution: out = (adj-premixed F) @ W^T + bias, fp16 MMA, fp32 accum.
// R7: shuffle-free premix (each thread owns a 4-row quad x 4 cols), MMA-first
// loop order. 256-thread CTA (M64 x N256), 2 CTAs/SM, cp.async 3-stage B ring.
// ============================================================================

#define KDIM    1024
#define NOUTD   256
#define MTILE   64
#define KC      64
#define NCHUNK  (KDIM / KC)          // 16
#define THREADS 256
#define ASLOT   (64 * 128)           // 8 KB per A slot (fp16, 128B rows)
#define BSTAGE  (256 * 128)          // 32 KB per B stage
#define SMEM_B0 (2 * ASLOT)          // 16384
#define SMEMB   (SMEM_B0 + 3 * BSTAGE)  // 114688 = 112 KB

__device__ __align__(16) __half WhalfG[NOUTD * KDIM];   // 512 KB scratch

// ---------------- helpers ----------------
__device__ __forceinline__ uint32_t smem_u32(const void* p) {
    uint32_t a;
    asm("{ .reg .u64 t; cvta.to.shared.u64 t, %1; cvt.u32.u64 %0, t; }" : "=r"(a) : "l"(p));
    return a;
}
__device__ __forceinline__ uint32_t swz(int row, int colbyte) {
    return (uint32_t)(row * 128 + (colbyte ^ ((row & 7) << 4)));
}
__device__ __forceinline__ void ldmatrix_x4(uint32_t& r0, uint32_t& r1,
                                            uint32_t& r2, uint32_t& r3, uint32_t addr) {
    asm volatile("ldmatrix.sync.aligned.m8n8.x4.shared.b16 {%0,%1,%2,%3}, [%4];"
                 : "=r"(r0), "=r"(r1), "=r"(r2), "=r"(r3) : "r"(addr));
}
__device__ __forceinline__ void mma16816(float* c, const uint32_t* a,
                                         uint32_t b0, uint32_t b1) {
    asm volatile("mma.sync.aligned.m16n8k16.row.col.f32.f16.f16.f32 "
                 "{%0,%1,%2,%3}, {%4,%5,%6,%7}, {%8,%9}, {%0,%1,%2,%3};"
                 : "+f"(c[0]), "+f"(c[1]), "+f"(c[2]), "+f"(c[3])
                 : "r"(a[0]), "r"(a[1]), "r"(a[2]), "r"(a[3]), "r"(b0), "r"(b1));
}
__device__ __forceinline__ uint32_t h2u(__half2 h) {
    return *reinterpret_cast<uint32_t*>(&h);
}
__device__ __forceinline__ void cp_async16(uint32_t dst, const void* src) {
    asm volatile("cp.async.cg.shared.global [%0], [%1], 16;" :: "r"(dst), "l"(src));
}
#define CP_COMMIT() asm volatile("cp.async.commit_group;" ::: "memory")
#define CP_WAIT1()  asm volatile("cp.async.wait_group 1;" ::: "memory")

// ---------------- kernel 1: W fp32 -> fp16 ----------------
__global__ void convW_kernel(const float* __restrict__ W) {
    int i = blockIdx.x * blockDim.x + threadIdx.x;        // 65536 threads, 4 f each
    float4 v = reinterpret_cast<const float4*>(W)[i];
    uint2 u = make_uint2(h2u(__floats2half2_rn(v.x, v.y)),
                         h2u(__floats2half2_rn(v.z, v.w)));
    reinterpret_cast<uint2*>(WhalfG)[i] = u;
}

// ---------------- kernel 2: fused premix + GEMM ----------------
__global__ void __launch_bounds__(THREADS, 2) gconv_gemm_kernel(
    const float* __restrict__ adj,   // [4,4]
    const float* __restrict__ F,     // [32768,1024]
    const float* __restrict__ bias,  // [256]
    float* __restrict__ out)         // [32768,256]
{
    extern __shared__ char smem[];
    const uint32_t sbase = smem_u32(smem);
    const int tid  = threadIdx.x;
    const int warp = tid >> 5;
    const int lane = tid & 31;
    const int wm   = warp & 1;       // 2 warps along M
    const int wn   = warp >> 1;      // 4 warps along N
    const size_t tile_row = (size_t)blockIdx.x * MTILE;

    // Full adj matrix per thread (needed for local zero-shfl premix)
    const float4 A0 = __ldg((const float4*)(adj + 0));
    const float4 A1 = __ldg((const float4*)(adj + 4));
    const float4 A2 = __ldg((const float4*)(adj + 8));
    const float4 A3 = __ldg((const float4*)(adj + 12));

    float c[2][8][4];
#pragma unroll
    for (int i = 0; i < 2; i++)
#pragma unroll
        for (int j = 0; j < 8; j++)
#pragma unroll
            for (int k = 0; k < 4; k++) c[i][j][k] = 0.f;

    // A staging: 4 source rows x 4 cols (quad-local, zero-shfl premix)
    const int quad = tid >> 4;       // 0..15  -> rows 4*quad .. 4*quad+3
    const int cg   = tid & 15;       // 0..15  -> cols cg*4 .. cg*4+3
    float4 ra[4];

    auto loadA = [&](int ch) {
        const float* ap = F + (tile_row + 4 * quad) * (size_t)KDIM + ch * KC + cg * 4;
#pragma unroll
        for (int m = 0; m < 4; m++)
            ra[m] = *reinterpret_cast<const float4*>(ap + (size_t)m * KDIM);
    };

    // premix locally: h_row(4q+n) = sum_m adj[n][m] * ra[m];  store 8B per row
    auto storeA = [&](int slot) {
        char* sa = smem + slot * ASLOT;
#pragma unroll
        for (int n = 0; n < 4; n++) {
            const float4 an = (n == 0) ? A0 : (n == 1) ? A1 : (n == 2) ? A2 : A3;
            float ox = an.x * ra[0].x + an.y * ra[1].x + an.z * ra[2].x + an.w * ra[3].x;
            float oy = an.x * ra[0].y + an.y * ra[1].y + an.z * ra[2].y + an.w * ra[3].y;
            float oz = an.x * ra[0].z + an.y * ra[1].z + an.z * ra[2].z + an.w * ra[3].z;
            float ow = an.x * ra[0].w + an.y * ra[1].w + an.z * ra[2].w + an.w * ra[3].w;
            uint2 u = make_uint2(h2u(__floats2half2_rn(ox, oy)),
                                 h2u(__floats2half2_rn(oz, ow)));
            *reinterpret_cast<uint2*>(sa + swz(4 * quad + n, cg * 8)) = u;
        }
    };

    // ---- B: cp.async fp16 W chunk into smem stage (128B per thread) ----
    auto cpasyncB = [&](int ch, int stage) {
        const uint32_t bs = sbase + SMEM_B0 + stage * BSTAGE;
#pragma unroll
        for (int i = 0; i < 8; i++) {
            const int u = tid + i * THREADS;     // 0..2047
            const int row = u >> 3;              // 0..255
            const int cb  = (u & 7) * 16;        // 0..112
            const char* src = reinterpret_cast<const char*>(WhalfG)
                              + (size_t)row * 2048 + ch * 128 + cb;
            cp_async16(bs + swz(row, cb), src);
        }
    };

    // ---- prologue ----
    cpasyncB(0, 0); CP_COMMIT();
    cpasyncB(1, 1); CP_COMMIT();
    loadA(0); storeA(0);
    loadA(1);

    // ---- main loop (MMA-first; premix/loads in the tensor shadow) ----
    for (int ch = 0; ch < NCHUNK; ch++) {
        CP_WAIT1();                 // B(ch) arrived (B(ch+1) may be in flight)
        __syncthreads();            // A(ch) visible; MMA(ch-1) done everywhere

        if (ch + 2 < NCHUNK) cpasyncB(ch + 2, (ch + 2) % 3);
        CP_COMMIT();                // commit every iter -> constant wait depth

        const uint32_t sa = sbase + (ch & 1) * ASLOT;
        const uint32_t sb = sbase + SMEM_B0 + (ch % 3) * BSTAGE;
#pragma unroll
        for (int ks = 0; ks < 4; ks++) {
            uint32_t a[2][4];
#pragma unroll
            for (int mf = 0; mf < 2; mf++) {
                const int row = wm * 32 + mf * 16 + (lane & 15);
                const int cb  = ks * 32 + ((lane >> 4) & 1) * 16;
                ldmatrix_x4(a[mf][0], a[mf][1], a[mf][2], a[mf][3], sa + swz(row, cb));
            }
            uint32_t b[4][4];
#pragma unroll
            for (int j = 0; j < 4; j++) {
                const int row = wn * 64 + j * 16 + (lane & 7) + ((lane >> 4) & 1) * 8;
                const int cb  = ks * 32 + ((lane >> 3) & 1) * 16;
                ldmatrix_x4(b[j][0], b[j][1], b[j][2], b[j][3], sb + swz(row, cb));
            }
#pragma unroll
            for (int mf = 0; mf < 2; mf++)
#pragma unroll
                for (int nf = 0; nf < 8; nf++)
                    mma16816(c[mf][nf], a[mf],
                             b[nf >> 1][(nf & 1) * 2], b[nf >> 1][(nf & 1) * 2 + 1]);
        }

        // premix + next-next A load AFTER the MMA block (tensor already running)
        if (ch + 1 < NCHUNK) storeA((ch + 1) & 1);  // slot free: MMA(ch-1) retired
        if (ch + 2 < NCHUNK) loadA(ch + 2);         // consumed after MMA(ch+1)
    }

    // ---- epilogue: + bias, store fp32 ----
    float2 bb[8];
#pragma unroll
    for (int nf = 0; nf < 8; nf++)
        bb[nf] = *reinterpret_cast<const float2*>(bias + wn * 64 + nf * 8 + (lane & 3) * 2);

#pragma unroll
    for (int mf = 0; mf < 2; mf++) {
#pragma unroll
        for (int nf = 0; nf < 8; nf++) {
            const size_t m = tile_row + wm * 32 + mf * 16 + (lane >> 2);
            const int n = wn * 64 + nf * 8 + (lane & 3) * 2;
            float2 o0 = make_float2(c[mf][nf][0] + bb[nf].x, c[mf][nf][1] + bb[nf].y);
            float2 o1 = make_float2(c[mf][nf][2] + bb[nf].x, c[mf][nf][3] + bb[nf].y);
            *reinterpret_cast<float2*>(out + m * NOUTD + n) = o0;
            *reinterpret_cast<float2*>(out + (m + 8) * NOUTD + n) = o1;
        }
    }
}

// ============================================================================
extern "C" void kernel_launch(void* const* d_in, const int* in_sizes, int n_in,
                              void* d_out, int out_size) {
    (void)in_sizes; (void)n_in; (void)out_size;
    const float* adj  = (const float*)d_in[0];   // [4,4]
    const float* F    = (const float*)d_in[1];   // [8192,4,1024]
    const float* W    = (const float*)d_in[2];   // [256,1024]
    const float* bias = (const float*)d_in[3];   // [256]
    float* out = (float*)d_out;                  // [8192,4,256]

    convW_kernel<<<256, 256>>>(W);

    cudaFuncSetAttribute(gconv_gemm_kernel,
                         cudaFuncAttributeMaxDynamicSharedMemorySize, SMEMB);
    gconv_gemm_kernel<<<32768 / MTILE, THREADS, SMEMB>>>(adj, F, bias, out);
}